// round 15
// baseline (speedup 1.0000x reference)
#include <cuda_runtime.h>
#include <cstdint>

#define TT 1024
#define NB 128
#define ND 11              // poly degree 10 -> 11 terms, G is 11x11
#define BARBIG 0x40000000u

// ---- device scratch (static only) ----
__device__ float4 g_duv[TT * 64];     // (de, du, dv, 0) per row — 4 MB
__device__ float g_Hm[NB][128];
__device__ float g_H2[16][128];
__device__ float g_L[ND], g_R[ND];
__device__ float g_sc[NB], g_sc2[16];
__device__ unsigned g_cnt[2];

// Race-free grid barrier, 2 slots (proven R7/R12).
__device__ __forceinline__ void gbar(int p, int tid)
{
    __threadfence();
    __syncthreads();
    if (tid == 0) {
        unsigned old = atomicAdd(&g_cnt[p], 1u);
        if (old == NB - 1u) {
            g_cnt[p ^ 1] = 0u;
            __threadfence();
            atomicExch(&g_cnt[p], BARBIG);
        } else {
            while (*((volatile unsigned*)&g_cnt[p]) < BARBIG) { }
        }
    }
    __syncthreads();
}

// ============================================================
// K1: dots — warp per row, 4 rows/warp, max occupancy.
//   g_duv[row] = (emb[cid].we1, emb[cid].wt0, emb[cid].wt1)
// ============================================================
__global__ __launch_bounds__(256) void dots_kernel(
    const int* __restrict__ cids,  const float* __restrict__ emb,
    const float* __restrict__ ecw, const float* __restrict__ elw,
    const float* __restrict__ tcw, const float* __restrict__ tlw)
{
    __shared__ __align__(16) float we1[256], wt0[256], wt1[256];

    int tid = threadIdx.x, lane = tid & 31, w = tid >> 5;

    // effective weights (per-block recompute, cheap)
    {
        int d = tid;
        float em1 = (d > 0)   ? elw[d-1] : 0.f;
        float e0v = elw[d];
        float ep1 = (d < 255) ? elw[d+1] : 0.f;
        we1[d] = ecw[3]*ep1 + ecw[4]*e0v + ecw[5]*em1;
        float tm1 = (d > 0)   ? tlw[d-1] : 0.f;
        float t0v = tlw[d];
        float tp1 = (d < 255) ? tlw[d+1] : 0.f;
        wt0[d] = tcw[0]*tp1 + tcw[1]*t0v + tcw[2]*tm1;
        wt1[d] = tcw[3]*tp1 + tcw[4]*t0v + tcw[5]*tm1;
    }
    __syncthreads();

    const float4* A4 = (const float4*)we1;
    const float4* B4 = (const float4*)wt0;
    const float4* C4 = (const float4*)wt1;
    float4 a0 = A4[lane*2], a1 = A4[lane*2+1];
    float4 b0 = B4[lane*2], b1 = B4[lane*2+1];
    float4 c0 = C4[lane*2], c1 = C4[lane*2+1];

    int row0 = (blockIdx.x * 8 + w) * 4;    // 4 consecutive rows per warp

    float4 X0[2], X1[2];
    auto loadr = [&](float4 (&X)[2], int row) {
        const float4* e4 = (const float4*)(emb + (size_t)__ldg(cids + row) * 256);
        X[0] = __ldg(e4 + lane * 2);
        X[1] = __ldg(e4 + lane * 2 + 1);
    };

    loadr(X0, row0);
    #pragma unroll
    for (int r = 0; r < 4; r++) {
        if (r + 1 < 4) { if (r & 1) loadr(X0, row0 + r + 1); else loadr(X1, row0 + r + 1); }
        float4 p = (r & 1) ? X1[0] : X0[0];
        float4 q = (r & 1) ? X1[1] : X0[1];
        float de = p.x*a0.x + p.y*a0.y + p.z*a0.z + p.w*a0.w
                 + q.x*a1.x + q.y*a1.y + q.z*a1.z + q.w*a1.w;
        float du = p.x*b0.x + p.y*b0.y + p.z*b0.z + p.w*b0.w
                 + q.x*b1.x + q.y*b1.y + q.z*b1.z + q.w*b1.w;
        float dv = p.x*c0.x + p.y*c0.y + p.z*c0.z + p.w*c0.w
                 + q.x*c1.x + q.y*c1.y + q.z*c1.z + q.w*c1.w;
        #pragma unroll
        for (int o = 16; o; o >>= 1) {
            de += __shfl_xor_sync(0xffffffffu, de, o);
            du += __shfl_xor_sync(0xffffffffu, du, o);
            dv += __shfl_xor_sync(0xffffffffu, dv, o);
        }
        if (lane == 0)
            g_duv[row0 + r] = make_float4(de, du, dv, 0.f);
    }
}

// ============================================================
// K2: fold — persistent 128x512, reads g_duv, builds G, folds tree.
// ============================================================
__global__ __launch_bounds__(512) void fold_kernel(
    const float* __restrict__ obs,
    const float* __restrict__ ecw,  const float* __restrict__ ecb,
    const float* __restrict__ elw,  const float* __restrict__ elb,
    const float* __restrict__ tcw,  const float* __restrict__ tcb,
    const float* __restrict__ tlw,  const float* __restrict__ tlb,
    float* __restrict__ out)
{
    __shared__ __align__(16) float we0[256];
    __shared__ float u_s[9][64], v_s[9][64], ek_s[9][64];
    __shared__ float od_s[9];
    __shared__ float Bt[ND][ND];
    __shared__ float red[16];
    __shared__ float s_ce, s_ct, s_mx;
    __shared__ float UP[64][11];
    __shared__ float Wt[ND][64];
    __shared__ float Gb[9][121];
    __shared__ float Hp[2][128];
    __shared__ float Gtmp[121];

    int tid  = threadIdx.x, b = blockIdx.x;
    int lane = tid & 31, w = tid >> 5;

    //========== A: effective we0 + scalar constants ==========
    if (tid < 256) {
        int d = tid;
        float em1 = (d > 0)   ? elw[d-1] : 0.f;
        float e0v = elw[d];
        float ep1 = (d < 255) ? elw[d+1] : 0.f;
        we0[d] = ecw[0]*ep1 + ecw[1]*e0v + ecw[2]*em1;
        float t0v = tlw[d];
        float ve = e0v, vt = t0v;
        #pragma unroll
        for (int o = 16; o; o >>= 1) {
            ve += __shfl_xor_sync(0xffffffffu, ve, o);
            vt += __shfl_xor_sync(0xffffffffu, vt, o);
        }
        if (lane == 0) { red[w] = ve; red[8 + w] = vt; }
    }
    __syncthreads();
    if (tid == 0) {
        float Se = 0.f, St = 0.f;
        #pragma unroll
        for (int i = 0; i < 8; i++) { Se += red[i]; St += red[8 + i]; }
        s_ce = ecb[0] * Se + elb[0];
        s_ct = tcb[0] * St + tlb[0];
    }
    __syncthreads();

    //========== B: Taylor coeffs of g(d)=exp(sigmoid(ct+d)), fp32 ==========
    if (tid == 0) {
        float p[12], q[12];
        float ct = s_ct;
        p[0] = 1.f / (1.f + expf(-ct));
        #pragma unroll
        for (int n = 0; n < 10; n++) {
            float acc = 0.f;
            for (int i = 0; i <= n; i++) acc += p[i] * p[n-i];
            p[n+1] = (p[n] - acc) / (float)(n + 1);
        }
        q[0] = expf(p[0]);
        #pragma unroll
        for (int n = 0; n < 10; n++) {
            float acc = 0.f;
            for (int i = 0; i <= n; i++) acc += (float)(i+1) * p[i+1] * q[n-i];
            q[n+1] = acc / (float)(n + 1);
        }
        float C[ND][ND];
        for (int n = 0; n < ND; n++) {
            C[n][0] = 1.f; C[n][n] = 1.f;
            for (int m = 1; m < n; m++) C[n][m] = C[n-1][m-1] + C[n-1][m];
        }
        for (int m = 0; m < ND; m++)
            for (int l = 0; l < ND; l++)
                Bt[m][l] = (m + l <= 10) ? q[m+l] * C[m+l][m] : 0.f;
    }

    //========== C: obs dots + read precomputed row dots ==========
    int f0  = 8 * b;
    int sLo = (b == 0)      ? 0 : 1;
    int sHi = (b == NB - 1) ? 7 : 8;

    if (w >= sLo && w <= sHi) {
        const float* op = obs + (size_t)(f0 + w) * 256;
        float od = 0.f;
        #pragma unroll
        for (int q8 = 0; q8 < 8; q8++)
            od += op[lane + 32*q8] * we0[lane + 32*q8];
        #pragma unroll
        for (int o = 16; o; o >>= 1) od += __shfl_xor_sync(0xffffffffu, od, o);
        if (lane == 0) od_s[w] = od;
    }
    __syncthreads();

    for (int i = tid + sLo * 64; i < (sHi + 1) * 64; i += 512) {
        float4 p = __ldcg(&g_duv[f0 * 64 + i]);
        int s = i >> 6, r = i & 63;
        u_s[s][r] = p.y;
        v_s[s][r] = p.z;
        float x  = p.x + od_s[s] + s_ce;
        float sg = __fdividef(1.f, 1.f + __expf(-x));
        ek_s[s][r] = __expf(sg);
    }
    __syncthreads();

    //========== D: per frame slot -> 11x11 G (or R vector) ==========
    for (int s = 1; s <= sHi; s++) {
        if (tid < 64) {
            float u = u_s[s][tid], pw = 1.f;
            UP[tid][0] = 1.f;
            #pragma unroll
            for (int l = 1; l <= 10; l++) { pw *= u; UP[tid][l] = pw; }
        }
        for (int e = tid; e < ND * 64; e += 512) {
            int m = e >> 6, k = e & 63;
            float v = v_s[s][k];
            float pw = 1.f, acc = 0.f;
            #pragma unroll
            for (int l = 0; l < ND; l++) { acc = fmaf(Bt[m][l], pw, acc); pw *= v; }
            Wt[m][k] = acc * ek_s[s][k];
        }
        __syncthreads();
        bool isR = (b == NB - 1 && s == 7);
        if (!isR) {
            if (tid < 121) {
                int m = tid / 11, l = tid - m * 11;
                float acc = 0.f;
                #pragma unroll 8
                for (int k = 0; k < 64; k++)
                    acc = fmaf(Wt[m][k], UP[k][l], acc);
                Gb[s][tid] = acc;
            }
        } else {
            if (tid < ND) {
                float acc = 0.f;
                for (int k = 0; k < 64; k++) acc += Wt[tid][k];
                g_R[tid] = acc;
            }
        }
        __syncthreads();
    }
    if (b == 0 && tid < ND) {
        float acc = 0.f;
        for (int j = 0; j < 64; j++) {
            float u = u_s[0][j], pw = 1.f;
            for (int i = 0; i < tid; i++) pw *= u;
            acc = fmaf(ek_s[0][j], pw, acc);
        }
        g_L[tid] = acc;
    }

    //========== E: fold this block's G chain ==========
    int ng = (b == NB - 1) ? 6 : 8;
    if (tid < 121) Hp[0][tid] = Gb[1][tid];
    __syncthreads();
    int cur = 0;
    for (int s = 2; s <= ng; s++) {
        if (tid < 121) {
            int m = tid / 11, l = tid - m * 11;
            float acc = 0.f;
            #pragma unroll
            for (int i = 0; i < ND; i++)
                acc = fmaf(Hp[cur][m*11 + i], Gb[s][i*11 + l], acc);
            Hp[cur ^ 1][tid] = acc;
        }
        cur ^= 1;
        __syncthreads();
    }
    {
        float vv = (tid < 121) ? fabsf(Hp[cur][tid]) : 0.f;
        #pragma unroll
        for (int o = 16; o; o >>= 1) vv = fmaxf(vv, __shfl_xor_sync(0xffffffffu, vv, o));
        if (lane == 0) red[w] = vv;
        __syncthreads();
        if (tid == 0) {
            float m = red[0];
            #pragma unroll
            for (int i = 1; i < 16; i++) m = fmaxf(m, red[i]);
            s_mx = m;
            g_sc[b] = logf(m);
        }
        __syncthreads();
        float inv = __fdividef(1.f, s_mx);
        if (tid < 121) g_Hm[b][tid] = Hp[cur][tid] * inv;
    }
    gbar(0, tid);

    //========== F: 16 blocks fold 8 H's each ==========
    if (b < 16) {
        if (tid < 121) Hp[0][tid] = __ldcg(&g_Hm[8*b][tid]);
        __syncthreads();
        int c2 = 0;
        for (int i = 1; i < 8; i++) {
            if (tid < 121) Gtmp[tid] = __ldcg(&g_Hm[8*b + i][tid]);
            __syncthreads();
            if (tid < 121) {
                int m = tid / 11, l = tid - m * 11;
                float acc = 0.f;
                #pragma unroll
                for (int q = 0; q < ND; q++)
                    acc = fmaf(Hp[c2][m*11 + q], Gtmp[q*11 + l], acc);
                Hp[c2 ^ 1][tid] = acc;
            }
            c2 ^= 1;
            __syncthreads();
        }
        float vv = (tid < 121) ? fabsf(Hp[c2][tid]) : 0.f;
        #pragma unroll
        for (int o = 16; o; o >>= 1) vv = fmaxf(vv, __shfl_xor_sync(0xffffffffu, vv, o));
        if (lane == 0) red[w] = vv;
        __syncthreads();
        if (tid == 0) {
            float m = red[0];
            #pragma unroll
            for (int i = 1; i < 16; i++) m = fmaxf(m, red[i]);
            s_mx = m;
            g_sc2[b] = logf(m);
        }
        __syncthreads();
        float inv = __fdividef(1.f, s_mx);
        if (tid < 121) g_H2[b][tid] = Hp[c2][tid] * inv;
    }
    gbar(1, tid);

    //========== G: block 0 folds 16, applies boundary vectors ==========
    if (b == 0) {
        if (tid < 121) Hp[0][tid] = __ldcg(&g_H2[0][tid]);
        __syncthreads();
        int c3 = 0;
        for (int i = 1; i < 16; i++) {
            if (tid < 121) Gtmp[tid] = __ldcg(&g_H2[i][tid]);
            __syncthreads();
            if (tid < 121) {
                int m = tid / 11, l = tid - m * 11;
                float acc = 0.f;
                #pragma unroll
                for (int q = 0; q < ND; q++)
                    acc = fmaf(Hp[c3][m*11 + q], Gtmp[q*11 + l], acc);
                Hp[c3 ^ 1][tid] = acc;
            }
            c3 ^= 1;
            __syncthreads();
        }
        float sv = (tid < NB) ? __ldcg(g_sc + tid) : 0.f;
        #pragma unroll
        for (int o = 16; o; o >>= 1) sv += __shfl_xor_sync(0xffffffffu, sv, o);
        if (lane == 0) red[w] = sv;
        __syncthreads();
        if (tid == 0) {
            float tot = red[0] + red[1] + red[2] + red[3];
            for (int i = 0; i < 16; i++) tot += g_sc2[i];
            float y[ND];
            for (int m = 0; m < ND; m++) {
                float acc = 0.f;
                for (int l = 0; l < ND; l++)
                    acc = fmaf(Hp[c3][m*11 + l], g_R[l], acc);
                y[m] = acc;
            }
            float z = 0.f;
            for (int m = 0; m < ND; m++) z = fmaf(g_L[m], y[m], z);
            out[0] = logf(z) + tot;
        }
    }
}

// ============================================================
extern "C" void kernel_launch(void* const* d_in, const int* in_sizes, int n_in,
                              void* d_out, int out_size)
{
    const float* obs = (const float*)d_in[0];
    const int*   cid = (const int*)  d_in[1];
    const float* emb = (const float*)d_in[2];
    const float* ecw = (const float*)d_in[3];
    const float* ecb = (const float*)d_in[4];
    const float* elw = (const float*)d_in[5];
    const float* elb = (const float*)d_in[6];
    const float* tcw = (const float*)d_in[7];
    const float* tcb = (const float*)d_in[8];
    const float* tlw = (const float*)d_in[9];
    const float* tlb = (const float*)d_in[10];
    float* out = (float*)d_out;

    dots_kernel<<<2048, 256>>>(cid, emb, ecw, elw, tcw, tlw);
    fold_kernel<<<NB, 512>>>(obs, ecw, ecb, elw, elb, tcw, tcb, tlw, tlb, out);
}

// round 16
// speedup vs baseline: 1.4322x; 1.4322x over previous
#include <cuda_runtime.h>
#include <cstdint>

#define TT 1024
#define ND 11              // poly degree 10 -> 11 terms, M is 11x11

// ---- device scratch (static only; fully rewritten every replay) ----
__device__ float4 g_duv[TT * 64];     // (de, du, dv, 0) per row — 4 MB
__device__ float  g_od[TT];
__device__ float  g_ce;
__device__ float  g_Bt[ND * ND];
__device__ float  g_G[TT][121];       // M_t for t = 1..1022
__device__ float  g_L[ND], g_R[ND];
__device__ float  g_Hm[128][121];
__device__ float  g_H2[16][121];
__device__ float  g_sc[128], g_sc2[16];

// ============================================================
// K1: dots — warp per row, 4 rows/warp, max occupancy (proven R15).
// ============================================================
__global__ __launch_bounds__(256) void dots_kernel(
    const int* __restrict__ cids,  const float* __restrict__ emb,
    const float* __restrict__ ecw, const float* __restrict__ elw,
    const float* __restrict__ tcw, const float* __restrict__ tlw)
{
    __shared__ __align__(16) float we1[256], wt0[256], wt1[256];

    int tid = threadIdx.x, lane = tid & 31, w = tid >> 5;
    {
        int d = tid;
        float em1 = (d > 0)   ? elw[d-1] : 0.f;
        float e0v = elw[d];
        float ep1 = (d < 255) ? elw[d+1] : 0.f;
        we1[d] = ecw[3]*ep1 + ecw[4]*e0v + ecw[5]*em1;
        float tm1 = (d > 0)   ? tlw[d-1] : 0.f;
        float t0v = tlw[d];
        float tp1 = (d < 255) ? tlw[d+1] : 0.f;
        wt0[d] = tcw[0]*tp1 + tcw[1]*t0v + tcw[2]*tm1;
        wt1[d] = tcw[3]*tp1 + tcw[4]*t0v + tcw[5]*tm1;
    }
    __syncthreads();

    const float4* A4 = (const float4*)we1;
    const float4* B4 = (const float4*)wt0;
    const float4* C4 = (const float4*)wt1;
    float4 a0 = A4[lane*2], a1 = A4[lane*2+1];
    float4 b0 = B4[lane*2], b1 = B4[lane*2+1];
    float4 c0 = C4[lane*2], c1 = C4[lane*2+1];

    int row0 = (blockIdx.x * 8 + w) * 4;

    float4 X0[2], X1[2];
    auto loadr = [&](float4 (&X)[2], int row) {
        const float4* e4 = (const float4*)(emb + (size_t)__ldg(cids + row) * 256);
        X[0] = __ldg(e4 + lane * 2);
        X[1] = __ldg(e4 + lane * 2 + 1);
    };

    loadr(X0, row0);
    #pragma unroll
    for (int r = 0; r < 4; r++) {
        if (r + 1 < 4) { if (r & 1) loadr(X0, row0 + r + 1); else loadr(X1, row0 + r + 1); }
        float4 p = (r & 1) ? X1[0] : X0[0];
        float4 q = (r & 1) ? X1[1] : X0[1];
        float de = p.x*a0.x + p.y*a0.y + p.z*a0.z + p.w*a0.w
                 + q.x*a1.x + q.y*a1.y + q.z*a1.z + q.w*a1.w;
        float du = p.x*b0.x + p.y*b0.y + p.z*b0.z + p.w*b0.w
                 + q.x*b1.x + q.y*b1.y + q.z*b1.z + q.w*b1.w;
        float dv = p.x*c0.x + p.y*c0.y + p.z*c0.z + p.w*c0.w
                 + q.x*c1.x + q.y*c1.y + q.z*c1.z + q.w*c1.w;
        #pragma unroll
        for (int o = 16; o; o >>= 1) {
            de += __shfl_xor_sync(0xffffffffu, de, o);
            du += __shfl_xor_sync(0xffffffffu, du, o);
            dv += __shfl_xor_sync(0xffffffffu, dv, o);
        }
        if (lane == 0)
            g_duv[row0 + r] = make_float4(de, du, dv, 0.f);
    }
}

// ============================================================
// K2: odce — obs dots (warp per frame) + ce + Taylor coeffs (block 0).
// ============================================================
__global__ __launch_bounds__(256) void odce_kernel(
    const float* __restrict__ obs,
    const float* __restrict__ ecw, const float* __restrict__ ecb,
    const float* __restrict__ elw, const float* __restrict__ elb,
    const float* __restrict__ tcw, const float* __restrict__ tcb,
    const float* __restrict__ tlw, const float* __restrict__ tlb)
{
    __shared__ float we0[256];
    __shared__ float red[16];

    int tid = threadIdx.x, b = blockIdx.x, lane = tid & 31, w = tid >> 5;
    int d = tid;
    float em1 = (d > 0)   ? elw[d-1] : 0.f;
    float e0v = elw[d];
    float ep1 = (d < 255) ? elw[d+1] : 0.f;
    we0[d] = ecw[0]*ep1 + ecw[1]*e0v + ecw[2]*em1;

    float ve = e0v, vt = tlw[d];
    #pragma unroll
    for (int o = 16; o; o >>= 1) {
        ve += __shfl_xor_sync(0xffffffffu, ve, o);
        vt += __shfl_xor_sync(0xffffffffu, vt, o);
    }
    if (lane == 0) { red[w] = ve; red[8 + w] = vt; }
    __syncthreads();

    if (b == 0 && tid == 0) {
        float Se = 0.f, St = 0.f;
        #pragma unroll
        for (int i = 0; i < 8; i++) { Se += red[i]; St += red[8 + i]; }
        g_ce = ecb[0] * Se + elb[0];
        float ct = tcb[0] * St + tlb[0];

        float p[12], q[12];
        p[0] = 1.f / (1.f + expf(-ct));
        #pragma unroll
        for (int n = 0; n < 10; n++) {
            float acc = 0.f;
            for (int i = 0; i <= n; i++) acc += p[i] * p[n-i];
            p[n+1] = (p[n] - acc) / (float)(n + 1);
        }
        q[0] = expf(p[0]);
        #pragma unroll
        for (int n = 0; n < 10; n++) {
            float acc = 0.f;
            for (int i = 0; i <= n; i++) acc += (float)(i+1) * p[i+1] * q[n-i];
            q[n+1] = acc / (float)(n + 1);
        }
        float C[ND][ND];
        for (int n = 0; n < ND; n++) {
            C[n][0] = 1.f; C[n][n] = 1.f;
            for (int m = 1; m < n; m++) C[n][m] = C[n-1][m-1] + C[n-1][m];
        }
        for (int m = 0; m < ND; m++)
            for (int l = 0; l < ND; l++)
                g_Bt[m * ND + l] = (m + l <= 10) ? q[m+l] * C[m+l][m] : 0.f;
    }

    // one warp per frame
    int t = b * 8 + w;
    const float* op = obs + (size_t)t * 256;
    float od = 0.f;
    #pragma unroll
    for (int q8 = 0; q8 < 8; q8++)
        od += op[lane + 32*q8] * we0[lane + 32*q8];
    #pragma unroll
    for (int o = 16; o; o >>= 1) od += __shfl_xor_sync(0xffffffffu, od, o);
    if (lane == 0) g_od[t] = od;
}

// ============================================================
// K3: gmat — block t builds M_t (11x11) from frame t only.
//   t=0 -> L vector, t=1023 -> R vector, else g_G[t].
// ============================================================
__global__ __launch_bounds__(128) void gmat_kernel()
{
    __shared__ float v_[64], ek_[64];
    __shared__ float UPs[64][11];
    __shared__ float Ws[11][64];
    __shared__ float Bs[121];

    int tid = threadIdx.x, t = blockIdx.x;

    if (tid < 121) Bs[tid] = __ldg(&g_Bt[tid]);
    if (tid < 64) {
        float4 p = __ldcg(&g_duv[t * 64 + tid]);
        v_[tid] = p.z;
        float x  = p.x + __ldcg(&g_od[t]) + g_ce;
        float sg = __fdividef(1.f, 1.f + __expf(-x));
        ek_[tid] = __expf(sg);
        float u = p.y, pw = 1.f;
        UPs[tid][0] = 1.f;
        #pragma unroll
        for (int l = 1; l <= 10; l++) { pw *= u; UPs[tid][l] = pw; }
    }
    __syncthreads();

    // Ws[m][k] = (sum_l Bt[m][l] v^l) * ek[k]
    #pragma unroll
    for (int e = tid; e < ND * 64; e += 128) {
        int m = e >> 6, k = e & 63;
        float v = v_[k], pw = 1.f, acc = 0.f;
        #pragma unroll
        for (int l = 0; l < ND; l++) { acc = fmaf(Bs[m*11 + l], pw, acc); pw *= v; }
        Ws[m][k] = acc * ek_[k];
    }
    __syncthreads();

    if (t == 0) {
        if (tid < ND) {                   // L[m] = sum_j ek[j] * u[j]^m
            float acc = 0.f;
            #pragma unroll 8
            for (int j = 0; j < 64; j++) acc = fmaf(ek_[j], UPs[j][tid], acc);
            g_L[tid] = acc;
        }
    } else if (t == TT - 1) {
        if (tid < ND) {                   // R[m] = sum_k Ws[m][k]
            float acc = 0.f;
            #pragma unroll 8
            for (int k = 0; k < 64; k++) acc += Ws[tid][k];
            g_R[tid] = acc;
        }
    } else {
        if (tid < 121) {                  // M_t[m][mp] = sum_k Ws[m][k] u^mp
            int m = tid / 11, mp = tid - m * 11;
            float acc = 0.f;
            #pragma unroll 8
            for (int k = 0; k < 64; k++)
                acc = fmaf(Ws[m][k], UPs[k][mp], acc);
            g_G[t][tid] = acc;
        }
    }
}

// ============================================================
// 11x11 smem fold helper (121 threads active)
// ============================================================
__device__ __forceinline__ void fold_step(const float* Hc, const float* Gn,
                                          float* Hn, int tid)
{
    if (tid < 121) {
        int m = tid / 11, l = tid - m * 11;
        float acc = 0.f;
        #pragma unroll
        for (int q = 0; q < ND; q++)
            acc = fmaf(Hc[m*11 + q], Gn[q*11 + l], acc);
        Hn[tid] = acc;
    }
}

__device__ __forceinline__ float blockmax121(float v, int tid, int lane, int w,
                                             float* red)
{
    #pragma unroll
    for (int o = 16; o; o >>= 1) v = fmaxf(v, __shfl_xor_sync(0xffffffffu, v, o));
    if (lane == 0) red[w] = v;
    __syncthreads();
    return fmaxf(fmaxf(red[0], red[1]), fmaxf(red[2], red[3]));
}

// ============================================================
// K4: fold8 — block b folds M_{8b+1..8b+8} -> g_Hm[b] (max-rescaled)
// ============================================================
__global__ __launch_bounds__(128) void fold8_kernel()
{
    __shared__ float Gs[8][121];
    __shared__ float Hp[2][121];
    __shared__ float red[4];

    int tid = threadIdx.x, b = blockIdx.x, lane = tid & 31, w = tid >> 5;
    int i0  = 8 * b + 1;
    int cnt = (b == 127) ? 6 : 8;

    for (int j = tid; j < cnt * 121; j += 128) {
        int i = j / 121, e = j - i * 121;
        Gs[i][e] = __ldcg(&g_G[i0 + i][e]);
    }
    __syncthreads();

    if (tid < 121) Hp[0][tid] = Gs[0][tid];
    __syncthreads();
    int cur = 0;
    for (int i = 1; i < cnt; i++) {
        fold_step(Hp[cur], Gs[i], Hp[cur ^ 1], tid);
        cur ^= 1;
        __syncthreads();
    }

    float mx = blockmax121((tid < 121) ? fabsf(Hp[cur][tid]) : 0.f,
                           tid, lane, w, red);
    if (tid == 0) g_sc[b] = logf(mx);
    float inv = __fdividef(1.f, mx);
    if (tid < 121) g_Hm[b][tid] = Hp[cur][tid] * inv;
}

// ============================================================
// K5: fold16 — block j folds g_Hm[8j..8j+7] -> g_H2[j]
// ============================================================
__global__ __launch_bounds__(128) void fold16_kernel()
{
    __shared__ float Gs[8][121];
    __shared__ float Hp[2][121];
    __shared__ float red[4];

    int tid = threadIdx.x, b = blockIdx.x, lane = tid & 31, w = tid >> 5;

    for (int j = tid; j < 8 * 121; j += 128) {
        int i = j / 121, e = j - i * 121;
        Gs[i][e] = __ldcg(&g_Hm[8 * b + i][e]);
    }
    __syncthreads();

    if (tid < 121) Hp[0][tid] = Gs[0][tid];
    __syncthreads();
    int cur = 0;
    for (int i = 1; i < 8; i++) {
        fold_step(Hp[cur], Gs[i], Hp[cur ^ 1], tid);
        cur ^= 1;
        __syncthreads();
    }

    float mx = blockmax121((tid < 121) ? fabsf(Hp[cur][tid]) : 0.f,
                           tid, lane, w, red);
    if (tid == 0) g_sc2[b] = logf(mx);
    float inv = __fdividef(1.f, mx);
    if (tid < 121) g_H2[b][tid] = Hp[cur][tid] * inv;
}

// ============================================================
// K6: final — fold 16 H2's, apply L/R, sum scales -> logZ
// ============================================================
__global__ __launch_bounds__(128) void final_kernel(float* __restrict__ out)
{
    __shared__ float Gs[16][121];
    __shared__ float Hp[2][121];
    __shared__ float red[4];

    int tid = threadIdx.x, lane = tid & 31, w = tid >> 5;

    for (int j = tid; j < 16 * 121; j += 128) {
        int i = j / 121, e = j - i * 121;
        Gs[i][e] = __ldcg(&g_H2[i][e]);
    }
    __syncthreads();

    if (tid < 121) Hp[0][tid] = Gs[0][tid];
    __syncthreads();
    int cur = 0;
    for (int i = 1; i < 16; i++) {
        fold_step(Hp[cur], Gs[i], Hp[cur ^ 1], tid);
        cur ^= 1;
        __syncthreads();
    }

    // scale sum: 128 g_sc + 16 g_sc2
    float sv = __ldcg(&g_sc[tid]) + ((tid < 16) ? __ldcg(&g_sc2[tid]) : 0.f);
    #pragma unroll
    for (int o = 16; o; o >>= 1) sv += __shfl_xor_sync(0xffffffffu, sv, o);
    if (lane == 0) red[w] = sv;
    __syncthreads();

    if (tid == 0) {
        float tot = red[0] + red[1] + red[2] + red[3];
        float y[ND];
        for (int m = 0; m < ND; m++) {
            float acc = 0.f;
            #pragma unroll
            for (int l = 0; l < ND; l++)
                acc = fmaf(Hp[cur][m*11 + l], g_R[l], acc);
            y[m] = acc;
        }
        float z = 0.f;
        #pragma unroll
        for (int m = 0; m < ND; m++) z = fmaf(g_L[m], y[m], z);
        out[0] = logf(z) + tot;
    }
}

// ============================================================
extern "C" void kernel_launch(void* const* d_in, const int* in_sizes, int n_in,
                              void* d_out, int out_size)
{
    const float* obs = (const float*)d_in[0];
    const int*   cid = (const int*)  d_in[1];
    const float* emb = (const float*)d_in[2];
    const float* ecw = (const float*)d_in[3];
    const float* ecb = (const float*)d_in[4];
    const float* elw = (const float*)d_in[5];
    const float* elb = (const float*)d_in[6];
    const float* tcw = (const float*)d_in[7];
    const float* tcb = (const float*)d_in[8];
    const float* tlw = (const float*)d_in[9];
    const float* tlb = (const float*)d_in[10];
    float* out = (float*)d_out;

    dots_kernel<<<2048, 256>>>(cid, emb, ecw, elw, tcw, tlw);
    odce_kernel<<<128, 256>>>(obs, ecw, ecb, elw, elb, tcw, tcb, tlw, tlb);
    gmat_kernel<<<TT, 128>>>();
    fold8_kernel<<<128, 128>>>();
    fold16_kernel<<<16, 128>>>();
    final_kernel<<<1, 128>>>(out);
}

// round 17
// speedup vs baseline: 1.8085x; 1.2628x over previous
#include <cuda_runtime.h>
#include <cstdint>

#define TT 1024
#define ND 11              // poly degree 10 -> 11 terms, M is 11x11

// ---- device scratch (static only; fully rewritten every replay) ----
__device__ float4 g_duv[TT * 64];     // (de, du, dv, 0) per row — 4 MB
__device__ float  g_od[TT];
__device__ float  g_ce;
__device__ float  g_Bt[ND * ND];
__device__ float  g_G[TT][121];       // M_t for t = 1..1022
__device__ float  g_L[ND], g_R[ND];
__device__ float  g_Hm[128][121];
__device__ float  g_H2[16][121];
__device__ float  g_sc[128], g_sc2[16];

// ============================================================
// 11x11 product helper: C = A * B, one thread per element (e < 121)
// ============================================================
__device__ __forceinline__ void prod11(const float* A, const float* B,
                                       float* C, int e)
{
    int m = e / 11, l = e - m * 11;
    float acc = 0.f;
    #pragma unroll
    for (int q = 0; q < ND; q++)
        acc = fmaf(A[m*11 + q], B[q*11 + l], acc);
    C[e] = acc;
}

// ============================================================
// K1: dots + od + ce/Taylor (fused). 2048 blocks x 256 threads.
//   every block: 8 warps x 4 rows of g_duv
//   blocks < 1024: warp 0 additionally computes g_od[blockIdx.x]
//   block 0, tid 0: g_ce + g_Bt (Taylor coeffs)
// ============================================================
__global__ __launch_bounds__(256) void dots_kernel(
    const int* __restrict__ cids,  const float* __restrict__ emb,
    const float* __restrict__ obs,
    const float* __restrict__ ecw, const float* __restrict__ ecb,
    const float* __restrict__ elw, const float* __restrict__ elb,
    const float* __restrict__ tcw, const float* __restrict__ tcb,
    const float* __restrict__ tlw, const float* __restrict__ tlb)
{
    __shared__ __align__(16) float we0[256], we1[256], wt0[256], wt1[256];
    __shared__ float red[16];

    int tid = threadIdx.x, b = blockIdx.x, lane = tid & 31, w = tid >> 5;
    {
        int d = tid;
        float em1 = (d > 0)   ? elw[d-1] : 0.f;
        float e0v = elw[d];
        float ep1 = (d < 255) ? elw[d+1] : 0.f;
        we0[d] = ecw[0]*ep1 + ecw[1]*e0v + ecw[2]*em1;
        we1[d] = ecw[3]*ep1 + ecw[4]*e0v + ecw[5]*em1;
        float tm1 = (d > 0)   ? tlw[d-1] : 0.f;
        float t0v = tlw[d];
        float tp1 = (d < 255) ? tlw[d+1] : 0.f;
        wt0[d] = tcw[0]*tp1 + tcw[1]*t0v + tcw[2]*tm1;
        wt1[d] = tcw[3]*tp1 + tcw[4]*t0v + tcw[5]*tm1;
        float ve = e0v, vt = t0v;
        #pragma unroll
        for (int o = 16; o; o >>= 1) {
            ve += __shfl_xor_sync(0xffffffffu, ve, o);
            vt += __shfl_xor_sync(0xffffffffu, vt, o);
        }
        if (lane == 0) { red[w] = ve; red[8 + w] = vt; }
    }
    __syncthreads();

    // block 0: ce + Taylor coefficients of g(d) = exp(sigmoid(ct + d))
    if (b == 0 && tid == 0) {
        float Se = 0.f, St = 0.f;
        #pragma unroll
        for (int i = 0; i < 8; i++) { Se += red[i]; St += red[8 + i]; }
        g_ce = ecb[0] * Se + elb[0];
        float ct = tcb[0] * St + tlb[0];

        float p[12], q[12];
        p[0] = 1.f / (1.f + expf(-ct));
        #pragma unroll
        for (int n = 0; n < 10; n++) {
            float acc = 0.f;
            for (int i = 0; i <= n; i++) acc += p[i] * p[n-i];
            p[n+1] = (p[n] - acc) / (float)(n + 1);
        }
        q[0] = expf(p[0]);
        #pragma unroll
        for (int n = 0; n < 10; n++) {
            float acc = 0.f;
            for (int i = 0; i <= n; i++) acc += (float)(i+1) * p[i+1] * q[n-i];
            q[n+1] = acc / (float)(n + 1);
        }
        float C[ND][ND];
        for (int n = 0; n < ND; n++) {
            C[n][0] = 1.f; C[n][n] = 1.f;
            for (int m = 1; m < n; m++) C[n][m] = C[n-1][m-1] + C[n-1][m];
        }
        for (int m = 0; m < ND; m++)
            for (int l = 0; l < ND; l++)
                g_Bt[m * ND + l] = (m + l <= 10) ? q[m+l] * C[m+l][m] : 0.f;
    }

    // blocks < 1024: warp 0 computes od for frame t = b
    if (b < TT && w == 0) {
        const float* op = obs + (size_t)b * 256;
        float od = 0.f;
        #pragma unroll
        for (int q8 = 0; q8 < 8; q8++)
            od += op[lane + 32*q8] * we0[lane + 32*q8];
        #pragma unroll
        for (int o = 16; o; o >>= 1) od += __shfl_xor_sync(0xffffffffu, od, o);
        if (lane == 0) g_od[b] = od;
    }

    // row dots: 8 warps x 4 rows
    const float4* A4 = (const float4*)we1;
    const float4* B4 = (const float4*)wt0;
    const float4* C4 = (const float4*)wt1;
    float4 a0 = A4[lane*2], a1 = A4[lane*2+1];
    float4 b0 = B4[lane*2], b1 = B4[lane*2+1];
    float4 c0 = C4[lane*2], c1 = C4[lane*2+1];

    int row0 = (b * 8 + w) * 4;

    float4 X0[2], X1[2];
    auto loadr = [&](float4 (&X)[2], int row) {
        const float4* e4 = (const float4*)(emb + (size_t)__ldg(cids + row) * 256);
        X[0] = __ldg(e4 + lane * 2);
        X[1] = __ldg(e4 + lane * 2 + 1);
    };

    loadr(X0, row0);
    #pragma unroll
    for (int r = 0; r < 4; r++) {
        if (r + 1 < 4) { if (r & 1) loadr(X0, row0 + r + 1); else loadr(X1, row0 + r + 1); }
        float4 p = (r & 1) ? X1[0] : X0[0];
        float4 q = (r & 1) ? X1[1] : X0[1];
        float de = p.x*a0.x + p.y*a0.y + p.z*a0.z + p.w*a0.w
                 + q.x*a1.x + q.y*a1.y + q.z*a1.z + q.w*a1.w;
        float du = p.x*b0.x + p.y*b0.y + p.z*b0.z + p.w*b0.w
                 + q.x*b1.x + q.y*b1.y + q.z*b1.z + q.w*b1.w;
        float dv = p.x*c0.x + p.y*c0.y + p.z*c0.z + p.w*c0.w
                 + q.x*c1.x + q.y*c1.y + q.z*c1.z + q.w*c1.w;
        #pragma unroll
        for (int o = 16; o; o >>= 1) {
            de += __shfl_xor_sync(0xffffffffu, de, o);
            du += __shfl_xor_sync(0xffffffffu, du, o);
            dv += __shfl_xor_sync(0xffffffffu, dv, o);
        }
        if (lane == 0)
            g_duv[row0 + r] = make_float4(de, du, dv, 0.f);
    }
}

// ============================================================
// K2: gmat — block t builds M_t (11x11) from frame t only.
// ============================================================
__global__ __launch_bounds__(128) void gmat_kernel()
{
    __shared__ float v_[64], ek_[64];
    __shared__ float UPs[64][11];
    __shared__ float Ws[11][64];
    __shared__ float Bs[121];

    int tid = threadIdx.x, t = blockIdx.x;

    if (tid < 121) Bs[tid] = __ldg(&g_Bt[tid]);
    if (tid < 64) {
        float4 p = __ldcg(&g_duv[t * 64 + tid]);
        v_[tid] = p.z;
        float x  = p.x + __ldcg(&g_od[t]) + g_ce;
        float sg = __fdividef(1.f, 1.f + __expf(-x));
        ek_[tid] = __expf(sg);
        float u = p.y, pw = 1.f;
        UPs[tid][0] = 1.f;
        #pragma unroll
        for (int l = 1; l <= 10; l++) { pw *= u; UPs[tid][l] = pw; }
    }
    __syncthreads();

    #pragma unroll
    for (int e = tid; e < ND * 64; e += 128) {
        int m = e >> 6, k = e & 63;
        float v = v_[k], pw = 1.f, acc = 0.f;
        #pragma unroll
        for (int l = 0; l < ND; l++) { acc = fmaf(Bs[m*11 + l], pw, acc); pw *= v; }
        Ws[m][k] = acc * ek_[k];
    }
    __syncthreads();

    if (t == 0) {
        if (tid < ND) {
            float acc = 0.f;
            #pragma unroll 8
            for (int j = 0; j < 64; j++) acc = fmaf(ek_[j], UPs[j][tid], acc);
            g_L[tid] = acc;
        }
    } else if (t == TT - 1) {
        if (tid < ND) {
            float acc = 0.f;
            #pragma unroll 8
            for (int k = 0; k < 64; k++) acc += Ws[tid][k];
            g_R[tid] = acc;
        }
    } else {
        if (tid < 121) {
            int m = tid / 11, mp = tid - m * 11;
            float acc = 0.f;
            #pragma unroll 8
            for (int k = 0; k < 64; k++)
                acc = fmaf(Ws[m][k], UPs[k][mp], acc);
            g_G[t][tid] = acc;
        }
    }
}

__device__ __forceinline__ float blockmax121_512(float v, int tid, int lane,
                                                 int w, float* red)
{
    #pragma unroll
    for (int o = 16; o; o >>= 1) v = fmaxf(v, __shfl_xor_sync(0xffffffffu, v, o));
    if (lane == 0) red[w] = v;
    __syncthreads();
    float m = red[0];
    #pragma unroll
    for (int i = 1; i < 16; i++) m = fmaxf(m, red[i]);
    return m;
}

// ============================================================
// K3: fold8 — tree fold of M_{8b+1..8b+8} -> g_Hm[b].  512 threads.
// ============================================================
__global__ __launch_bounds__(512) void fold8_kernel()
{
    __shared__ float Gs[8][121];
    __shared__ float Ps[4][121];
    __shared__ float red[16];

    int tid = threadIdx.x, b = blockIdx.x, lane = tid & 31, w = tid >> 5;
    int i0  = 8 * b + 1;
    int cnt = (b == 127) ? 6 : 8;

    for (int j = tid; j < cnt * 121; j += 512) {
        int i = j / 121, e = j - i * 121;
        Gs[i][e] = __ldcg(&g_G[i0 + i][e]);
    }
    __syncthreads();

    int g = tid >> 7, e = tid & 127;
    // round 1: pairwise products (order-preserving)
    if (cnt == 8) {
        if (e < 121) prod11(Gs[2*g], Gs[2*g + 1], Ps[g], e);
        __syncthreads();
        if (g < 2 && e < 121) prod11(Ps[2*g], Ps[2*g + 1], Gs[g], e);
        __syncthreads();
        if (tid < 121) prod11(Gs[0], Gs[1], Ps[0], tid);
    } else {   // cnt == 6: ((G0G1)(G2G3)) * (G4G5)
        if (g < 3 && e < 121) prod11(Gs[2*g], Gs[2*g + 1], Ps[g], e);
        __syncthreads();
        if (g == 0 && e < 121) prod11(Ps[0], Ps[1], Gs[0], e);
        __syncthreads();
        if (tid < 121) prod11(Gs[0], Ps[2], Ps[0], tid);
    }
    __syncthreads();

    float mx = blockmax121_512((tid < 121) ? fabsf(Ps[0][tid]) : 0.f,
                               tid, lane, w, red);
    if (tid == 0) g_sc[b] = logf(mx);
    float inv = __fdividef(1.f, mx);
    if (tid < 121) g_Hm[b][tid] = Ps[0][tid] * inv;
}

// ============================================================
// K4: fold16 — block j tree-folds g_Hm[8j..8j+7] -> g_H2[j]. 512 threads.
// ============================================================
__global__ __launch_bounds__(512) void fold16_kernel()
{
    __shared__ float Gs[8][121];
    __shared__ float Ps[4][121];
    __shared__ float red[16];

    int tid = threadIdx.x, b = blockIdx.x, lane = tid & 31, w = tid >> 5;

    for (int j = tid; j < 8 * 121; j += 512) {
        int i = j / 121, e = j - i * 121;
        Gs[i][e] = __ldcg(&g_Hm[8 * b + i][e]);
    }
    __syncthreads();

    int g = tid >> 7, e = tid & 127;
    if (e < 121) prod11(Gs[2*g], Gs[2*g + 1], Ps[g], e);
    __syncthreads();
    if (g < 2 && e < 121) prod11(Ps[2*g], Ps[2*g + 1], Gs[g], e);
    __syncthreads();
    if (tid < 121) prod11(Gs[0], Gs[1], Ps[0], tid);
    __syncthreads();

    float mx = blockmax121_512((tid < 121) ? fabsf(Ps[0][tid]) : 0.f,
                               tid, lane, w, red);
    if (tid == 0) g_sc2[b] = logf(mx);
    float inv = __fdividef(1.f, mx);
    if (tid < 121) g_H2[b][tid] = Ps[0][tid] * inv;
}

// ============================================================
// K5: final — tree fold of 16 H2's + L/R + scale sum. 1 block x 512.
// ============================================================
__global__ __launch_bounds__(512) void final_kernel(float* __restrict__ out)
{
    __shared__ float Gs[16][121];
    __shared__ float Ps[8][121];
    __shared__ float red[16];

    int tid = threadIdx.x, lane = tid & 31, w = tid >> 5;

    for (int j = tid; j < 16 * 121; j += 512) {
        int i = j / 121, e = j - i * 121;
        Gs[i][e] = __ldcg(&g_H2[i][e]);
    }
    __syncthreads();

    int g = tid >> 7, e = tid & 127;
    // r1: 8 products (each group handles 2)
    if (e < 121) {
        prod11(Gs[2*g],       Gs[2*g + 1],       Ps[g],     e);
        prod11(Gs[2*(g+4)],   Gs[2*(g+4) + 1],   Ps[g + 4], e);
    }
    __syncthreads();
    // r2: 4 products
    if (e < 121) prod11(Ps[2*g], Ps[2*g + 1], Gs[g], e);
    __syncthreads();
    // r3: 2 products
    if (g < 2 && e < 121) prod11(Gs[2*g], Gs[2*g + 1], Ps[g], e);
    __syncthreads();
    // r4: 1 product
    if (tid < 121) prod11(Ps[0], Ps[1], Gs[0], tid);
    __syncthreads();

    // scale sum: 128 g_sc + 16 g_sc2 (512 threads, first 128 carry values)
    float sv = (tid < 128) ? __ldcg(&g_sc[tid]) : 0.f;
    if (tid < 16) sv += __ldcg(&g_sc2[tid]);
    #pragma unroll
    for (int o = 16; o; o >>= 1) sv += __shfl_xor_sync(0xffffffffu, sv, o);
    if (lane == 0) red[w] = sv;
    __syncthreads();

    if (tid == 0) {
        float tot = 0.f;
        #pragma unroll
        for (int i = 0; i < 16; i++) tot += red[i];
        float y[ND];
        for (int m = 0; m < ND; m++) {
            float acc = 0.f;
            #pragma unroll
            for (int l = 0; l < ND; l++)
                acc = fmaf(Gs[0][m*11 + l], g_R[l], acc);
            y[m] = acc;
        }
        float z = 0.f;
        #pragma unroll
        for (int m = 0; m < ND; m++) z = fmaf(g_L[m], y[m], z);
        out[0] = logf(z) + tot;
    }
}

// ============================================================
extern "C" void kernel_launch(void* const* d_in, const int* in_sizes, int n_in,
                              void* d_out, int out_size)
{
    const float* obs = (const float*)d_in[0];
    const int*   cid = (const int*)  d_in[1];
    const float* emb = (const float*)d_in[2];
    const float* ecw = (const float*)d_in[3];
    const float* ecb = (const float*)d_in[4];
    const float* elw = (const float*)d_in[5];
    const float* elb = (const float*)d_in[6];
    const float* tcw = (const float*)d_in[7];
    const float* tcb = (const float*)d_in[8];
    const float* tlw = (const float*)d_in[9];
    const float* tlb = (const float*)d_in[10];
    float* out = (float*)d_out;

    dots_kernel<<<2048, 256>>>(cid, emb, obs, ecw, ecb, elw, elb,
                               tcw, tcb, tlw, tlb);
    gmat_kernel<<<TT, 128>>>();
    fold8_kernel<<<128, 512>>>();
    fold16_kernel<<<16, 512>>>();
    final_kernel<<<1, 512>>>(out);
}